// round 1
// baseline (speedup 1.0000x reference)
#include <cuda_runtime.h>
#include <cuda_bf16.h>

// Problem: B=16, N=256, F=64, H=128
//   d[b,i,j]   = ||r[b,i]-r[b,j]||  (0 on coincident)
//   g_f(d)     = softplus( sum_h softplus(d*w1_h+b1_h) * W2[h,f] + b2_f )
//   out[b,i,f] = softplus( sum_j g_f(d_ij) * f[b,j,f] )
//
// g is a smooth function of the SCALAR d -> tabulate g on a 320-point grid over
// [0, sqrt(3)] and linearly interpolate (abs err ~2e-5, far below 1e-3 tol).

#define Bsz   16
#define Nsz   256
#define Fsz   64
#define Hsz   128
#define NPTS  320
#define TI    4            // i-rows per block
#define DMAXF 1.7320509f   // sqrt(3), max possible distance for r in [0,1)^3

__device__ float g_table[NPTS * Fsz];   // scratch: the tabulated MLP

__device__ __forceinline__ float sp(float x) {
    // numerically stable softplus, matches jax.nn.softplus in fp32
    return fmaxf(x, 0.0f) + log1pf(expf(-fabsf(x)));
}

// ---------------------------------------------------------------------------
// Kernel 1: build g_table[p][f] = g_f(p * DMAX/(NPTS-1))
// ---------------------------------------------------------------------------
__global__ void build_table_kernel(const float* __restrict__ w1,
                                   const float* __restrict__ b1,
                                   const float* __restrict__ W2,
                                   const float* __restrict__ b2) {
    __shared__ float h[Hsz];
    const int p = blockIdx.x;
    const int t = threadIdx.x;          // 0..127
    const float d = p * (DMAXF / (NPTS - 1));

    h[t] = sp(d * w1[t] + b1[t]);
    __syncthreads();

    if (t < Fsz) {
        float s = b2[t];
        #pragma unroll 8
        for (int k = 0; k < Hsz; k++)
            s += h[k] * W2[k * Fsz + t];
        g_table[p * Fsz + t] = sp(s);
    }
}

// ---------------------------------------------------------------------------
// Kernel 2: main message-passing kernel.
// Block = 256 threads, handles TI consecutive i rows for one batch b.
// Smem: full table copy (80KB) + r coords + per-i distance row + reduce buf.
// 86KB smem -> 2 CTAs/SM.
// ---------------------------------------------------------------------------
__global__ __launch_bounds__(256, 2)
void mp_kernel(const float* __restrict__ r,
               const float* __restrict__ fin,
               float* __restrict__ out) {
    extern __shared__ float smem[];
    float* sT    = smem;                       // NPTS*64 = 20480 floats
    float* sx    = sT + NPTS * Fsz;            // 256
    float* sy    = sx + Nsz;                   // 256
    float* sz    = sy + Nsz;                   // 256
    int*   sk    = (int*)(sz + Nsz);           // 256
    float* sfr   = (float*)(sk + Nsz);         // 256
    float* sred  = sfr + Nsz;                  // 256

    const int tid = threadIdx.x;
    const int b   = blockIdx.x >> 6;           // 64 blocks per batch
    const int i0  = (blockIdx.x & 63) * TI;

    // ---- load table into smem (vectorized) ----
    {
        float4* dst = (float4*)sT;
        const float4* src = (const float4*)g_table;
        #pragma unroll
        for (int idx = tid; idx < NPTS * (Fsz / 4); idx += 256)
            dst[idx] = src[idx];
    }
    // ---- load coordinates for this batch ----
    {
        const float* rb = r + (size_t)b * Nsz * 3;
        sx[tid] = rb[tid * 3 + 0];
        sy[tid] = rb[tid * 3 + 1];
        sz[tid] = rb[tid * 3 + 2];
    }
    __syncthreads();

    const int fl = tid & 63;                   // f lane
    const int jg = tid >> 6;                   // j group 0..3
    const float* fb = fin + (size_t)b * Nsz * Fsz;
    const float INV_DELTA = (float)(NPTS - 1) / DMAXF;

    for (int ii = 0; ii < TI; ii++) {
        const int i = i0 + ii;

        // phase 1: all 256 threads compute the distance row d[i][tid]
        {
            const float dx = sx[i] - sx[tid];
            const float dy = sy[i] - sy[tid];
            const float dz = sz[i] - sz[tid];
            const float s  = dx * dx + dy * dy + dz * dz;
            const float d  = (s > 0.0f) ? sqrtf(s) : 0.0f;
            float u = d * INV_DELTA;
            int   k = (int)u;
            if (k > NPTS - 2) k = NPTS - 2;
            sk[tid]  = k;
            sfr[tid] = u - (float)k;
        }
        __syncthreads();

        // phase 2: 64 f-lanes x 4 j-groups accumulate
        float acc = 0.0f;
        #pragma unroll 8
        for (int j = jg; j < Nsz; j += 4) {
            const int   k = sk[j];             // warp-broadcast
            const float t = sfr[j];            // warp-broadcast
            const float t0 = sT[k * Fsz + fl];
            const float t1 = sT[(k + 1) * Fsz + fl];
            const float g  = fmaf(t, t1 - t0, t0);
            acc = fmaf(g, __ldg(&fb[j * Fsz + fl]), acc);
        }
        sred[tid] = acc;
        __syncthreads();

        if (jg == 0) {
            const float v = sred[fl] + sred[Fsz + fl] +
                            sred[2 * Fsz + fl] + sred[3 * Fsz + fl];
            out[((size_t)b * Nsz + i) * Fsz + fl] = sp(v);
        }
        __syncthreads();   // protect sk/sfr/sred before next i
    }
}

// ---------------------------------------------------------------------------
extern "C" void kernel_launch(void* const* d_in, const int* in_sizes, int n_in,
                              void* d_out, int out_size) {
    const float* r_batch = (const float*)d_in[0];   // [16,256,3]
    const float* f_batch = (const float*)d_in[1];   // [16,256,64]
    const float* w1      = (const float*)d_in[2];   // [128]
    const float* b1      = (const float*)d_in[3];   // [128]
    const float* W2      = (const float*)d_in[4];   // [128,64]
    const float* b2      = (const float*)d_in[5];   // [64]
    float* out = (float*)d_out;                     // [16,256,64]

    build_table_kernel<<<NPTS, Hsz>>>(w1, b1, W2, b2);

    const size_t smem_bytes = (NPTS * Fsz + 6 * Nsz) * sizeof(float); // 88,064 B
    cudaFuncSetAttribute(mp_kernel,
                         cudaFuncAttributeMaxDynamicSharedMemorySize,
                         (int)smem_bytes);
    mp_kernel<<<Bsz * (Nsz / TI), 256, smem_bytes>>>(r_batch, f_batch, out);
}

// round 2
// speedup vs baseline: 2.0326x; 2.0326x over previous
#include <cuda_runtime.h>
#include <cuda_fp16.h>

// B=16, N=256, F=64, H=128
//   g_f(d) = softplus( softplus(d*w1+b1) @ W2 + b2 )  — scalar-input MLP,
//   tabulated at NPTS points over [0, sqrt(3)] and lerped (fp16 value+slope).
//   out[b,i,f] = softplus( sum_j g_f(d_ij) * f[b,j,f] )

#define Bsz   16
#define Nsz   256
#define Fsz   64
#define Hsz   128
#define NPTS  128
#define DMAXF 1.7320509f   // sqrt(3)

__device__ float g_val[NPTS * Fsz];          // fp32 table (build stage)
__device__ uint2 g_pack[NPTS * (Fsz / 2)];   // per (k, f-pair): {half2 val, half2 slope}

__device__ __forceinline__ float sp(float x) {
    return fmaxf(x, 0.0f) + log1pf(expf(-fabsf(x)));
}

// ---------------------------------------------------------------------------
// Stage 1: fp32 table  g_val[p][f] = g_f(p * DMAX/(NPTS-1))
// ---------------------------------------------------------------------------
__global__ void build_table_kernel(const float* __restrict__ w1,
                                   const float* __restrict__ b1,
                                   const float* __restrict__ W2,
                                   const float* __restrict__ b2) {
    __shared__ float h[Hsz];
    const int p = blockIdx.x;
    const int t = threadIdx.x;                 // 0..127
    const float d = p * (DMAXF / (NPTS - 1));
    h[t] = sp(fmaf(d, w1[t], b1[t]));
    __syncthreads();
    if (t < Fsz) {
        float s = b2[t];
        #pragma unroll 8
        for (int k = 0; k < Hsz; k++)
            s = fmaf(h[k], W2[k * Fsz + t], s);
        g_val[p * Fsz + t] = sp(s);
    }
}

// ---------------------------------------------------------------------------
// Stage 2: pack into fp16 {value, slope} pairs, 8B per (k, f-pair)
// ---------------------------------------------------------------------------
__global__ void pack_table_kernel() {
    const int idx = blockIdx.x * blockDim.x + threadIdx.x;   // NPTS*32 entries
    if (idx >= NPTS * (Fsz / 2)) return;
    const int k = idx >> 5;
    const int fp = idx & 31;
    const float v0 = g_val[k * Fsz + 2 * fp];
    const float v1 = g_val[k * Fsz + 2 * fp + 1];
    const int k1 = (k < NPTS - 1) ? k + 1 : k;
    const float u0 = g_val[k1 * Fsz + 2 * fp];
    const float u1 = g_val[k1 * Fsz + 2 * fp + 1];
    const __half2 val = __floats2half2_rn(v0, v1);
    const __half2 slo = __floats2half2_rn(u0 - v0, u1 - v1);
    uint2 e;
    e.x = *(const unsigned int*)&val;
    e.y = *(const unsigned int*)&slo;
    g_pack[idx] = e;
}

// ---------------------------------------------------------------------------
// Stage 3: main kernel.
// Block = 256 threads (8 warps) -> (batch b, 8 consecutive i-rows).
// Warp w owns j-chunk [w*32, w*32+32); f[b, chunk, :] lives in 64 registers.
// Per (i,j): 1 LDS.64 broadcast (t,koff) + 1 LDS.64 table + HFMA2 lerp
// covering all 64 f (2 per lane). One block reduction at the end.
// ---------------------------------------------------------------------------
__global__ __launch_bounds__(256, 2)
void mp_kernel(const float* __restrict__ r,
               const float* __restrict__ fin,
               float* __restrict__ out) {
    extern __shared__ char smem_raw[];
    uint2*  sT   = (uint2*)smem_raw;                 // NPTS*32   (32 KB)
    float2* skt  = (float2*)(sT + NPTS * 32);        // 8*32      ( 2 KB)
    float2* sred = skt + 8 * 32;                     // 8*8*32    (16 KB)
    float*  sx   = (float*)(sred + 8 * 8 * 32);      // 256
    float*  sy   = sx + Nsz;                         // 256
    float*  sz   = sy + Nsz;                         // 256

    const int tid  = threadIdx.x;
    const int w    = tid >> 5;
    const int lane = tid & 31;
    const int b    = blockIdx.x >> 5;                // 32 blocks per batch
    const int i0   = (blockIdx.x & 31) * 8;

    // cooperative table load (32 KB, uint4)
    {
        uint4* dst = (uint4*)sT;
        const uint4* src = (const uint4*)g_pack;
        #pragma unroll
        for (int idx = tid; idx < NPTS * 16; idx += 256)
            dst[idx] = src[idx];
    }
    // coords for this batch
    {
        const float* rb = r + (size_t)b * Nsz * 3;
        sx[tid] = rb[tid * 3 + 0];
        sy[tid] = rb[tid * 3 + 1];
        sz[tid] = rb[tid * 3 + 2];
    }
    // f chunk into registers: freg[jl] = f[b, w*32+jl, 2*lane .. 2*lane+1]
    float2 freg[32];
    {
        const float2* fb2 = (const float2*)(fin + (size_t)b * Nsz * Fsz);
        #pragma unroll
        for (int jl = 0; jl < 32; jl++)
            freg[jl] = fb2[(w * 32 + jl) * 32 + lane];
    }
    __syncthreads();

    const int myj = w * 32 + lane;
    const float rx = sx[myj], ry = sy[myj], rz = sz[myj];
    const float INVD = (float)(NPTS - 1) / DMAXF;
    const uint2* tw = sT + lane;

    for (int ii = 0; ii < 8; ii++) {
        const int i = i0 + ii;

        // this lane's pair (i, myj): interval + fraction
        const float dx = sx[i] - rx;
        const float dy = sy[i] - ry;
        const float dz = sz[i] - rz;
        const float s2 = dx * dx + dy * dy + dz * dz;
        const float d  = (s2 > 0.0f) ? sqrtf(s2) : 0.0f;
        const float u  = d * INVD;
        int k = (int)u;
        if (k > NPTS - 2) k = NPTS - 2;
        const float t = u - (float)k;
        const __half2 th2 = __float2half2_rn(t);

        float2 kt;
        kt.x = __uint_as_float(*(const unsigned int*)&th2);
        kt.y = __int_as_float(k << 5);               // element offset k*32
        __syncwarp();
        skt[w * 32 + lane] = kt;
        __syncwarp();

        float accx = 0.0f, accy = 0.0f;
        #pragma unroll
        for (int jl = 0; jl < 32; jl++) {
            const float2 c = skt[w * 32 + jl];       // broadcast
            const unsigned tb = __float_as_uint(c.x);
            const int ko = __float_as_int(c.y);
            const uint2 e = tw[ko];                   // conflict-free LDS.64
            const __half2 vv = *(const __half2*)&e.x;
            const __half2 ss = *(const __half2*)&e.y;
            const __half2 gh = __hfma2(*(const __half2*)&tb, ss, vv);
            const float2 g = __half22float2(gh);
            accx = fmaf(g.x, freg[jl].x, accx);
            accy = fmaf(g.y, freg[jl].y, accy);
        }
        sred[(w * 8 + ii) * 32 + lane] = make_float2(accx, accy);
    }
    __syncthreads();

    // warp w reduces + outputs row i0+w
    float sumx = 0.0f, sumy = 0.0f;
    #pragma unroll
    for (int p = 0; p < 8; p++) {
        const float2 v = sred[(p * 8 + w) * 32 + lane];
        sumx += v.x;
        sumy += v.y;
    }
    float2 o;
    o.x = sp(sumx);
    o.y = sp(sumy);
    ((float2*)out)[((size_t)b * Nsz + i0 + w) * 32 + lane] = o;
}

// ---------------------------------------------------------------------------
extern "C" void kernel_launch(void* const* d_in, const int* in_sizes, int n_in,
                              void* d_out, int out_size) {
    const float* r_batch = (const float*)d_in[0];   // [16,256,3]
    const float* f_batch = (const float*)d_in[1];   // [16,256,64]
    const float* w1      = (const float*)d_in[2];   // [128]
    const float* b1      = (const float*)d_in[3];   // [128]
    const float* W2      = (const float*)d_in[4];   // [128,64]
    const float* b2      = (const float*)d_in[5];   // [64]
    float* out = (float*)d_out;                     // [16,256,64]

    build_table_kernel<<<NPTS, Hsz>>>(w1, b1, W2, b2);
    pack_table_kernel<<<(NPTS * (Fsz / 2) + 255) / 256, 256>>>();

    const size_t smem_bytes = NPTS * 32 * 8 + 8 * 32 * 8 + 8 * 8 * 32 * 8
                            + 3 * Nsz * 4;          // 54,272 B
    static bool attr_set = false;
    if (!attr_set) {
        cudaFuncSetAttribute(mp_kernel,
                             cudaFuncAttributeMaxDynamicSharedMemorySize,
                             (int)smem_bytes);
        attr_set = true;
    }
    mp_kernel<<<Bsz * 32, 256, smem_bytes>>>(r_batch, f_batch, out);
}

// round 4
// speedup vs baseline: 2.2054x; 1.0850x over previous
#include <cuda_runtime.h>
#include <cuda_fp16.h>

// B=16, N=256, F=64, H=128
//   g_f(d) = softplus( softplus(d*w1+b1) @ W2 + b2 )  — scalar-input MLP,
//   tabulated at NPTS points over [0, sqrt(3)], fp16 {value,slope} lerp.
//   out[b,i,f] = softplus( sum_j g_f(d_ij) * f[b,j,f] )

#define Bsz   16
#define Nsz   256
#define Fsz   64
#define Hsz   128
#define NPTS  128
#define DMAXF 1.7320509f   // sqrt(3)

__device__ uint2 g_pack[NPTS * (Fsz / 2)];   // per (k, f-pair): {half2 val, half2 slope}

__device__ __forceinline__ float sp(float x) {
    return fmaxf(x, 0.0f) + log1pf(expf(-fabsf(x)));
}

// ---------------------------------------------------------------------------
// Fused table build + pack. Grid=32, block=256.
// Block p0 computes table rows [4*p0, 4*p0+4] (5 rows; last one for slopes),
// then packs its 4 rows into g_pack as fp16 {value, slope}.
// ---------------------------------------------------------------------------
__global__ void table_kernel(const float* __restrict__ w1,
                             const float* __restrict__ b1,
                             const float* __restrict__ W2,
                             const float* __restrict__ b2) {
    __shared__ float W2s[Hsz * Fsz];   // 32 KB
    __shared__ float h5[5 * Hsz];      // 2.5 KB
    __shared__ float gbuf[5 * Fsz];    // 1.25 KB

    const int tid = threadIdx.x;
    const int p0  = blockIdx.x * 4;

    // stage W2 (vectorized)
    {
        float4* dst = (float4*)W2s;
        const float4* src = (const float4*)W2;
        #pragma unroll
        for (int idx = tid; idx < Hsz * Fsz / 4; idx += 256)
            dst[idx] = src[idx];
    }
    // hidden layer for 5 rows
    for (int idx = tid; idx < 5 * Hsz; idx += 256) {
        const int q  = idx >> 7;
        const int hh = idx & (Hsz - 1);
        int p = p0 + q; if (p > NPTS - 1) p = NPTS - 1;
        const float d = p * (DMAXF / (NPTS - 1));
        h5[idx] = sp(fmaf(d, w1[hh], b1[hh]));
    }
    __syncthreads();

    // output layer: 5*64 = 320 dot products of length 128 (all smem)
    for (int idx = tid; idx < 5 * Fsz; idx += 256) {
        const int q = idx >> 6;
        const int f = idx & (Fsz - 1);
        float s = b2[f];
        const float* hq = h5 + q * Hsz;
        #pragma unroll 8
        for (int k = 0; k < Hsz; k++)
            s = fmaf(hq[k], W2s[k * Fsz + f], s);
        gbuf[idx] = sp(s);
    }
    __syncthreads();

    // pack 4 rows x 32 f-pairs
    if (tid < 128) {
        const int q  = tid >> 5;
        const int fp = tid & 31;
        const float v0 = gbuf[q * Fsz + 2 * fp];
        const float v1 = gbuf[q * Fsz + 2 * fp + 1];
        const float u0 = gbuf[(q + 1) * Fsz + 2 * fp];
        const float u1 = gbuf[(q + 1) * Fsz + 2 * fp + 1];
        const __half2 val = __floats2half2_rn(v0, v1);
        const __half2 slo = __floats2half2_rn(u0 - v0, u1 - v1);
        uint2 e;
        e.x = *(const unsigned int*)&val;
        e.y = *(const unsigned int*)&slo;
        g_pack[(p0 + q) * 32 + fp] = e;
    }
}

// ---------------------------------------------------------------------------
// Main kernel. Block = 256 threads (8 warps) -> (batch b, 8 i-rows).
// Warp w owns j-chunk [w*32, w*32+32); f[b,chunk,:] in registers.
// Per (i,j): SHFL the packed (k, t), one conflict-free LDS.64 of the fp16
// {val,slope} entry, HFMA2 lerp for 2 f's, fp32 accumulate.
// ---------------------------------------------------------------------------
__global__ __launch_bounds__(256, 2)
void mp_kernel(const float* __restrict__ r,
               const float* __restrict__ fin,
               float* __restrict__ out) {
    extern __shared__ char smem_raw[];
    uint2*  sT   = (uint2*)smem_raw;                 // NPTS*32 uint2 (32 KB)
    float2* sred = (float2*)(sT + NPTS * 32);        // 8*8*32 float2 (16 KB)
    float*  sx   = (float*)(sred + 8 * 8 * 32);      // 256
    float*  sy   = sx + Nsz;
    float*  sz   = sy + Nsz;

    const int tid  = threadIdx.x;
    const int w    = tid >> 5;
    const int lane = tid & 31;
    const int b    = blockIdx.x >> 5;                // 32 blocks per batch
    const int i0   = (blockIdx.x & 31) * 8;

    // cooperative table load (32 KB)
    {
        uint4* dst = (uint4*)sT;
        const uint4* src = (const uint4*)g_pack;
        #pragma unroll
        for (int idx = tid; idx < NPTS * 16; idx += 256)
            dst[idx] = src[idx];
    }
    {
        const float* rb = r + (size_t)b * Nsz * 3;
        sx[tid] = rb[tid * 3 + 0];
        sy[tid] = rb[tid * 3 + 1];
        sz[tid] = rb[tid * 3 + 2];
    }
    // f chunk into registers: freg[jl] = f[b, w*32+jl, 2*lane..2*lane+1]
    float2 freg[32];
    {
        const float2* fb2 = (const float2*)(fin + (size_t)b * Nsz * Fsz);
        #pragma unroll
        for (int jl = 0; jl < 32; jl++)
            freg[jl] = fb2[(w * 32 + jl) * 32 + lane];
    }
    __syncthreads();

    const int myj = w * 32 + lane;
    const float rx = sx[myj], ry = sy[myj], rz = sz[myj];
    const float INVD = (float)(NPTS - 1) / DMAXF;
    const char* twb = (const char*)(sT + lane);

    for (int ii = 0; ii < 8; ii++) {
        const int i = i0 + ii;

        // this lane's pair (i, myj): interval k + fraction t, packed
        const float dx = sx[i] - rx;
        const float dy = sy[i] - ry;
        const float dz = sz[i] - rz;
        const float s2 = dx * dx + dy * dy + dz * dz;
        const float d  = (s2 > 0.0f) ? sqrtf(s2) : 0.0f;
        const float u  = d * INVD;
        int k = (int)u;
        if (k > NPTS - 2) k = NPTS - 2;
        const float t = u - (float)k;
        const __half th = __float2half_rn(t);
        const unsigned myv = ((unsigned)k << 16) |
                             (unsigned)(*(const unsigned short*)&th);

        float accx = 0.0f, accy = 0.0f;
        #pragma unroll
        for (int jl = 0; jl < 32; jl++) {
            const unsigned pv = __shfl_sync(0xffffffffu, myv, jl);
            const uint2 e = *(const uint2*)(twb + ((pv & 0xFFFF0000u) >> 8));
            const unsigned tb = __byte_perm(pv, pv, 0x1010);   // half2(t,t)
            const __half2 gh = __hfma2(*(const __half2*)&tb,
                                       *(const __half2*)&e.y,
                                       *(const __half2*)&e.x);
            const float2 g = __half22float2(gh);
            accx = fmaf(g.x, freg[jl].x, accx);
            accy = fmaf(g.y, freg[jl].y, accy);
        }
        sred[(w * 8 + ii) * 32 + lane] = make_float2(accx, accy);
    }
    __syncthreads();

    // warp w reduces + writes row i0+w
    float sumx = 0.0f, sumy = 0.0f;
    #pragma unroll
    for (int p = 0; p < 8; p++) {
        const float2 v = sred[(p * 8 + w) * 32 + lane];
        sumx += v.x;
        sumy += v.y;
    }
    float2 o;
    o.x = sp(sumx);
    o.y = sp(sumy);
    ((float2*)out)[((size_t)b * Nsz + i0 + w) * 32 + lane] = o;
}

// ---------------------------------------------------------------------------
extern "C" void kernel_launch(void* const* d_in, const int* in_sizes, int n_in,
                              void* d_out, int out_size) {
    const float* r_batch = (const float*)d_in[0];   // [16,256,3]
    const float* f_batch = (const float*)d_in[1];   // [16,256,64]
    const float* w1      = (const float*)d_in[2];   // [128]
    const float* b1      = (const float*)d_in[3];   // [128]
    const float* W2      = (const float*)d_in[4];   // [128,64]
    const float* b2      = (const float*)d_in[5];   // [64]
    float* out = (float*)d_out;                     // [16,256,64]

    table_kernel<<<NPTS / 4, 256>>>(w1, b1, W2, b2);

    const size_t smem_bytes = NPTS * 32 * 8 + 8 * 8 * 32 * 8 + 3 * Nsz * 4;
    static bool attr_set = false;
    if (!attr_set) {
        cudaFuncSetAttribute(mp_kernel,
                             cudaFuncAttributeMaxDynamicSharedMemorySize,
                             (int)smem_bytes);
        attr_set = true;
    }
    mp_kernel<<<Bsz * 32, 256, smem_bytes>>>(r_batch, f_batch, out);
}

// round 14
// speedup vs baseline: 2.6459x; 1.1997x over previous
#include <cuda_runtime.h>
#include <cuda_fp16.h>

// B=16, N=256, F=64, H=128
//   g_f(d) = softplus( softplus(d*w1+b1) @ W2 + b2 )  — scalar-input MLP.
//   Tabulated at NPTS=512 points over [0, sqrt(3)], fp16 values,
//   nearest-neighbor lookup (err ~2e-4 per g, averages out over j).
//   out[b,i,f] = softplus( sum_j g_f(d_ij) * f[b,j,f] )

#define Bsz   16
#define Nsz   256
#define Fsz   64
#define Hsz   128
#define NPTS  512
#define DMAXF 1.7320509f   // sqrt(3)

__device__ unsigned g_half[NPTS * (Fsz / 2)];   // half2 per (k, f-pair); row = 128B

__device__ __forceinline__ float sp(float x) {
    return fmaxf(x, 0.0f) + log1pf(expf(-fabsf(x)));
}

// ---------------------------------------------------------------------------
// Table build: grid=NPTS/4 blocks x 256 threads, 4 rows per block.
// W2 staged in smem; everything else trivial.
// ---------------------------------------------------------------------------
__global__ void table_kernel(const float* __restrict__ w1,
                             const float* __restrict__ b1,
                             const float* __restrict__ W2,
                             const float* __restrict__ b2) {
    __shared__ float W2s[Hsz * Fsz];   // 32 KB
    __shared__ float h4[4 * Hsz];      // 2 KB
    __shared__ float gbuf[4 * Fsz];    // 1 KB

    const int tid = threadIdx.x;
    const int p0  = blockIdx.x * 4;

    {   // stage W2
        float4* dst = (float4*)W2s;
        const float4* src = (const float4*)W2;
        #pragma unroll
        for (int idx = tid; idx < Hsz * Fsz / 4; idx += 256)
            dst[idx] = src[idx];
    }
    // hidden layer for 4 rows
    #pragma unroll
    for (int idx = tid; idx < 4 * Hsz; idx += 256) {
        const int q  = idx >> 7;
        const int hh = idx & (Hsz - 1);
        const float d = (p0 + q) * (DMAXF / (NPTS - 1));
        h4[idx] = sp(fmaf(d, w1[hh], b1[hh]));
    }
    __syncthreads();

    // output layer: 4*64 = 256 dots of length 128 (one per thread)
    {
        const int q = tid >> 6;
        const int f = tid & (Fsz - 1);
        float s = b2[f];
        const float* hq = h4 + q * Hsz;
        #pragma unroll 8
        for (int k = 0; k < Hsz; k++)
            s = fmaf(hq[k], W2s[k * Fsz + f], s);
        gbuf[tid] = sp(s);
    }
    __syncthreads();

    // pack 4 rows x 32 f-pairs as half2
    if (tid < 128) {
        const int q  = tid >> 5;
        const int fp = tid & 31;
        const __half2 v = __floats2half2_rn(gbuf[q * Fsz + 2 * fp],
                                            gbuf[q * Fsz + 2 * fp + 1]);
        g_half[(p0 + q) * 32 + fp] = *(const unsigned*)&v;
    }
}

// ---------------------------------------------------------------------------
// Main kernel. Block = 256 threads (8 warps) -> (batch b, 8 i-rows).
// Warp w owns j-chunk [w*32, w*32+32); f[b,chunk,:] in registers (float2/lane).
// Per (i,j): LDS.32 broadcast of the row byte-offset + LDS.32 table (half2
// for 2 f's) + 2 cvt + 2 FFMA. 2 crossbar phases per pair.
// ---------------------------------------------------------------------------
__global__ __launch_bounds__(256, 2)
void mp_kernel(const float* __restrict__ r,
               const float* __restrict__ fin,
               float* __restrict__ out) {
    extern __shared__ char smem_raw[];
    unsigned* sT   = (unsigned*)smem_raw;                // NPTS*32 u32 (64 KB)
    float2*   sred = (float2*)(sT + NPTS * 32);          // 8*8*32 float2 (16 KB)
    float*    sx   = (float*)(sred + 8 * 8 * 32);        // 256
    float*    sy   = sx + Nsz;
    float*    sz   = sy + Nsz;
    int*      skt  = (int*)(sz + Nsz);                   // 8*32 ints (1 KB)

    const int tid  = threadIdx.x;
    const int w    = tid >> 5;
    const int lane = tid & 31;
    const int b    = blockIdx.x >> 5;                    // 32 blocks per batch
    const int i0   = (blockIdx.x & 31) * 8;

    // cooperative table load (64 KB)
    {
        uint4* dst = (uint4*)sT;
        const uint4* src = (const uint4*)g_half;
        #pragma unroll
        for (int idx = tid; idx < NPTS * 8; idx += 256)
            dst[idx] = src[idx];
    }
    {
        const float* rb = r + (size_t)b * Nsz * 3;
        sx[tid] = rb[tid * 3 + 0];
        sy[tid] = rb[tid * 3 + 1];
        sz[tid] = rb[tid * 3 + 2];
    }
    // f chunk into registers: freg[jl] = f[b, w*32+jl, 2*lane..2*lane+1]
    float2 freg[32];
    {
        const float2* fb2 = (const float2*)(fin + (size_t)b * Nsz * Fsz);
        #pragma unroll
        for (int jl = 0; jl < 32; jl++)
            freg[jl] = fb2[(w * 32 + jl) * 32 + lane];
    }
    __syncthreads();

    const int myj = w * 32 + lane;
    const float rx = sx[myj], ry = sy[myj], rz = sz[myj];
    const float INVD = (float)(NPTS - 1) / DMAXF;
    const char* tb = (const char*)sT + lane * 4;   // this lane's column base
    int* sktw = skt + w * 32;

    for (int ii = 0; ii < 8; ii++) {
        const int i = i0 + ii;

        // nearest table row for pair (i, myj)
        const float dx = sx[i] - rx;
        const float dy = sy[i] - ry;
        const float dz = sz[i] - rz;
        const float s2 = dx * dx + dy * dy + dz * dz;
        const float d  = (s2 > 0.0f) ? sqrtf(s2) : 0.0f;
        int k = (int)(d * INVD + 0.5f);
        if (k > NPTS - 1) k = NPTS - 1;
        __syncwarp();
        sktw[lane] = k << 7;                 // row byte offset (128B rows)
        __syncwarp();

        float accx = 0.0f, accy = 0.0f;
        #pragma unroll
        for (int jl = 0; jl < 32; jl++) {
            const int ko = sktw[jl];                         // LDS.32 broadcast
            const unsigned vh = *(const unsigned*)(tb + ko); // LDS.32, no conflict
            const float2 g = __half22float2(*(const __half2*)&vh);
            accx = fmaf(g.x, freg[jl].x, accx);
            accy = fmaf(g.y, freg[jl].y, accy);
        }
        sred[(w * 8 + ii) * 32 + lane] = make_float2(accx, accy);
    }
    __syncthreads();

    // warp w reduces across the 8 warps' partials + writes row i0+w
    float sumx = 0.0f, sumy = 0.0f;
    #pragma unroll
    for (int p = 0; p < 8; p++) {
        const float2 v = sred[(p * 8 + w) * 32 + lane];
        sumx += v.x;
        sumy += v.y;
    }
    float2 o;
    o.x = sp(sumx);
    o.y = sp(sumy);
    ((float2*)out)[((size_t)b * Nsz + i0 + w) * 32 + lane] = o;
}

// ---------------------------------------------------------------------------
extern "C" void kernel_launch(void* const* d_in, const int* in_sizes, int n_in,
                              void* d_out, int out_size) {
    const float* r_batch = (const float*)d_in[0];   // [16,256,3]
    const float* f_batch = (const float*)d_in[1];   // [16,256,64]
    const float* w1      = (const float*)d_in[2];   // [128]
    const float* b1      = (const float*)d_in[3];   // [128]
    const float* W2      = (const float*)d_in[4];   // [128,64]
    const float* b2      = (const float*)d_in[5];   // [64]
    float* out = (float*)d_out;                     // [16,256,64]

    table_kernel<<<NPTS / 4, 256>>>(w1, b1, W2, b2);

    const size_t smem_bytes = NPTS * 32 * 4      // table  64 KB
                            + 8 * 8 * 32 * 8     // sred   16 KB
                            + 3 * Nsz * 4        // coords  3 KB
                            + 8 * 32 * 4;        // skt     1 KB
    static bool attr_set = false;
    if (!attr_set) {
        cudaFuncSetAttribute(mp_kernel,
                             cudaFuncAttributeMaxDynamicSharedMemorySize,
                             (int)smem_bytes);
        attr_set = true;
    }
    mp_kernel<<<Bsz * 32, 256, smem_bytes>>>(r_batch, f_batch, out);
}

// round 17
// speedup vs baseline: 3.1554x; 1.1926x over previous
#include <cuda_runtime.h>
#include <cuda_fp16.h>

// B=16, N=256, F=64, H=128
//   g_f(d) = softplus( softplus(d*w1+b1) @ W2 + b2 )  — scalar-input MLP.
//   NPTS=512-point fp16 table over [0, sqrt(3)], nearest-neighbor lookup.
//   out[b,i,f] = softplus( sum_j g_f(d_ij) * f[b,j,f] )
// Inner loop: uint4-batched offset broadcast + conflict-free half2 table LDS
// + HFMA2 accumulate (fp32 flush every 8 j).

#define Bsz   16
#define Nsz   256
#define Fsz   64
#define Hsz   128
#define NPTS  512
#define TI    16           // i-rows per block
#define DMAXF 1.7320509f   // sqrt(3)

__device__ unsigned g_half[NPTS * (Fsz / 2)];   // half2 per (k, f-pair); row = 128B

__device__ __forceinline__ float sp(float x) {
    return fmaxf(x, 0.0f) + log1pf(expf(-fabsf(x)));
}

// ---------------------------------------------------------------------------
// Table build: grid=NPTS/4 x 256 threads, 4 rows per block (unchanged).
// ---------------------------------------------------------------------------
__global__ void table_kernel(const float* __restrict__ w1,
                             const float* __restrict__ b1,
                             const float* __restrict__ W2,
                             const float* __restrict__ b2) {
    __shared__ float W2s[Hsz * Fsz];   // 32 KB
    __shared__ float h4[4 * Hsz];
    __shared__ float gbuf[4 * Fsz];

    const int tid = threadIdx.x;
    const int p0  = blockIdx.x * 4;

    {
        float4* dst = (float4*)W2s;
        const float4* src = (const float4*)W2;
        #pragma unroll
        for (int idx = tid; idx < Hsz * Fsz / 4; idx += 256)
            dst[idx] = src[idx];
    }
    #pragma unroll
    for (int idx = tid; idx < 4 * Hsz; idx += 256) {
        const int q  = idx >> 7;
        const int hh = idx & (Hsz - 1);
        const float d = (p0 + q) * (DMAXF / (NPTS - 1));
        h4[idx] = sp(fmaf(d, w1[hh], b1[hh]));
    }
    __syncthreads();
    {
        const int q = tid >> 6;
        const int f = tid & (Fsz - 1);
        float s = b2[f];
        const float* hq = h4 + q * Hsz;
        #pragma unroll 8
        for (int k = 0; k < Hsz; k++)
            s = fmaf(hq[k], W2s[k * Fsz + f], s);
        gbuf[tid] = sp(s);
    }
    __syncthreads();
    if (tid < 128) {
        const int q  = tid >> 5;
        const int fp = tid & 31;
        const __half2 v = __floats2half2_rn(gbuf[q * Fsz + 2 * fp],
                                            gbuf[q * Fsz + 2 * fp + 1]);
        g_half[(p0 + q) * 32 + fp] = *(const unsigned*)&v;
    }
}

// ---------------------------------------------------------------------------
// Main kernel. Block = 256 threads (8 warps) -> (batch b, 16 i-rows).
// Grid = 256 blocks -> single wave on 296 2-CTA slots.
// ---------------------------------------------------------------------------
__global__ __launch_bounds__(256, 2)
void mp_kernel(const float* __restrict__ r,
               const float* __restrict__ fin,
               float* __restrict__ out) {
    extern __shared__ char smem_raw[];
    unsigned* sT   = (unsigned*)smem_raw;                // NPTS*32 u32 (64 KB)
    float2*   sred = (float2*)(sT + NPTS * 32);          // 8*8*32 float2 (16 KB)
    float*    sx   = (float*)(sred + 8 * 8 * 32);        // 256
    float*    sy   = sx + Nsz;
    float*    sz   = sy + Nsz;
    uint4*    skt4 = (uint4*)(sz + Nsz);                 // 8 warps * 8 uint4 (1 KB)

    const int tid  = threadIdx.x;
    const int w    = tid >> 5;
    const int lane = tid & 31;
    const int b    = blockIdx.x >> 4;                    // 16 blocks per batch
    const int i0   = (blockIdx.x & 15) * TI;

    // cooperative table load (64 KB)
    {
        uint4* dst = (uint4*)sT;
        const uint4* src = (const uint4*)g_half;
        #pragma unroll
        for (int idx = tid; idx < NPTS * 8; idx += 256)
            dst[idx] = src[idx];
    }
    {
        const float* rb = r + (size_t)b * Nsz * 3;
        sx[tid] = rb[tid * 3 + 0];
        sy[tid] = rb[tid * 3 + 1];
        sz[tid] = rb[tid * 3 + 2];
    }
    // f chunk as half2: fregh[jl] = half2(f[b, w*32+jl, 2*lane], f[..., 2*lane+1])
    __half2 fregh[32];
    {
        const float2* fb2 = (const float2*)(fin + (size_t)b * Nsz * Fsz);
        #pragma unroll
        for (int jl = 0; jl < 32; jl++)
            fregh[jl] = __float22half2_rn(fb2[(w * 32 + jl) * 32 + lane]);
    }
    __syncthreads();

    const int myj = w * 32 + lane;
    const float rx = sx[myj], ry = sy[myj], rz = sz[myj];
    const float INVD = (float)(NPTS - 1) / DMAXF;
    const char* tb = (const char*)sT + lane * 4;         // lane's column base
    unsigned*    sktw  = (unsigned*)(skt4 + w * 8);
    const uint4* sktw4 = skt4 + w * 8;
    const __half2 hz = __float2half2_rn(0.0f);

    for (int half = 0; half < 2; half++) {
        for (int ii = 0; ii < 8; ii++) {
            const int i = i0 + half * 8 + ii;

            // nearest table row for pair (i, myj)
            const float dx = sx[i] - rx;
            const float dy = sy[i] - ry;
            const float dz = sz[i] - rz;
            const float s2 = dx * dx + dy * dy + dz * dz;
            const float d  = (s2 > 0.0f) ? sqrtf(s2) : 0.0f;
            int k = (int)(d * INVD + 0.5f);
            if (k > NPTS - 1) k = NPTS - 1;
            __syncwarp();
            sktw[lane] = (unsigned)(k << 7);     // row byte offset (128B rows)
            __syncwarp();

            float accx = 0.0f, accy = 0.0f;
            __half2 acc = hz;
            #pragma unroll
            for (int g = 0; g < 8; g++) {
                const uint4 o = sktw4[g];        // LDS.128 broadcast: 4 offsets
                const unsigned v0 = *(const unsigned*)(tb + o.x);
                acc = __hfma2(*(const __half2*)&v0, fregh[g * 4 + 0], acc);
                const unsigned v1 = *(const unsigned*)(tb + o.y);
                acc = __hfma2(*(const __half2*)&v1, fregh[g * 4 + 1], acc);
                const unsigned v2 = *(const unsigned*)(tb + o.z);
                acc = __hfma2(*(const __half2*)&v2, fregh[g * 4 + 2], acc);
                const unsigned v3 = *(const unsigned*)(tb + o.w);
                acc = __hfma2(*(const __half2*)&v3, fregh[g * 4 + 3], acc);
                if (g & 1) {                      // fp32 flush every 8 j
                    const float2 t = __half22float2(acc);
                    accx += t.x;
                    accy += t.y;
                    acc = hz;
                }
            }
            sred[(w * 8 + ii) * 32 + lane] = make_float2(accx, accy);
        }
        __syncthreads();

        // warp w reduces + writes row i0 + half*8 + w
        float sumx = 0.0f, sumy = 0.0f;
        #pragma unroll
        for (int p = 0; p < 8; p++) {
            const float2 v = sred[(p * 8 + w) * 32 + lane];
            sumx += v.x;
            sumy += v.y;
        }
        float2 o;
        o.x = sp(sumx);
        o.y = sp(sumy);
        ((float2*)out)[((size_t)b * Nsz + i0 + half * 8 + w) * 32 + lane] = o;
        __syncthreads();   // protect sred before next half reuses it
    }
}

// ---------------------------------------------------------------------------
extern "C" void kernel_launch(void* const* d_in, const int* in_sizes, int n_in,
                              void* d_out, int out_size) {
    const float* r_batch = (const float*)d_in[0];   // [16,256,3]
    const float* f_batch = (const float*)d_in[1];   // [16,256,64]
    const float* w1      = (const float*)d_in[2];   // [128]
    const float* b1      = (const float*)d_in[3];   // [128]
    const float* W2      = (const float*)d_in[4];   // [128,64]
    const float* b2      = (const float*)d_in[5];   // [64]
    float* out = (float*)d_out;                     // [16,256,64]

    table_kernel<<<NPTS / 4, 256>>>(w1, b1, W2, b2);

    const size_t smem_bytes = NPTS * 32 * 4      // table  64 KB
                            + 8 * 8 * 32 * 8     // sred   16 KB
                            + 3 * Nsz * 4        // coords  3 KB
                            + 8 * 8 * 16;        // skt4    1 KB
    static bool attr_set = false;
    if (!attr_set) {
        cudaFuncSetAttribute(mp_kernel,
                             cudaFuncAttributeMaxDynamicSharedMemorySize,
                             (int)smem_bytes);
        attr_set = true;
    }
    mp_kernel<<<Bsz * (Nsz / TI), 256, smem_bytes>>>(r_batch, f_batch, out);
}